// round 13
// baseline (speedup 1.0000x reference)
#include <cuda_runtime.h>
#include <math.h>

// ---------------- problem constants ----------------
#define DXV   10000
#define DRV   5000
#define NANC  2000
#define NNODE 18000     // DXV + SPLIT*NANC
#define Dm    128
#define ECNT  200000
#define NBV   640       // B*V
#define NCODE 80
#define NDX   40
#define LBL   2000
#define MAXDEG 192
#define ANCCAP 96       // per-row nonzero capacity (mean ~20, Poisson tail ~1e-14)

#define B_H    563      // ceil(18000/32)
#define B_DR   157      // ceil(5000/32)
#define B_SDX  313      // ceil(10000/32)
#define B_CNT  391      // ceil(200000/512)
#define NF4    (DXV * NANC / 4)          // 5,000,000 float4 in A
#define B_ASC  ((NF4 + 511) / 512)       // 9766 blocks, 512 f4 each

typedef unsigned long long ULL;

// ---------------- scratch ----------------
__device__ float g_h[NNODE * Dm];
__device__ float g_el[NNODE];
__device__ float g_er[NNODE];
__device__ int   g_count[DXV];      // zero at load; re-zeroed by k_scatter each call
__device__ int   g_rowoff[DXV + 1];
__device__ int   g_rank[ECNT];
__device__ int   g_eid[ECNT];
__device__ int   g_anccnt[DXV];     // zero at load; re-zeroed by k_aggCE each call
__device__ float g_ancval[DXV * ANCCAP];
__device__ int   g_ancidx[DXV * ANCCAP];
__device__ float g_dxALLonto[DXV * Dm];
__device__ float g_SdxA[DXV * Dm];  // static half: dxEmb @ attnW[0:128]
__device__ float g_Sdx[DXV * Dm];
__device__ float g_Sdrug[DRV * Dm];
__device__ float g_visit[NBV * 2 * Dm];

// ---------------- helpers ----------------
__device__ __forceinline__ float warpSum(float x) {
    #pragma unroll
    for (int o = 16; o; o >>= 1) x += __shfl_xor_sync(0xffffffffu, x, o);
    return x;
}
__device__ __forceinline__ float warpMax(float x) {
    #pragma unroll
    for (int o = 16; o; o >>= 1) x = fmaxf(x, __shfl_xor_sync(0xffffffffu, x, o));
    return x;
}
__device__ __forceinline__ float blockSum128(float x, float* sh) {
    int w = threadIdx.x >> 5, l = threadIdx.x & 31;
    x = warpSum(x);
    if (l == 0) sh[w] = x;
    __syncthreads();
    float r = sh[0] + sh[1] + sh[2] + sh[3];
    __syncthreads();
    return r;
}
__device__ __forceinline__ float blockMax128(float x, float* sh) {
    int w = threadIdx.x >> 5, l = threadIdx.x & 31;
    x = warpMax(x);
    if (l == 0) sh[w] = x;
    __syncthreads();
    float r = fmaxf(fmaxf(sh[0], sh[1]), fmaxf(sh[2], sh[3]));
    __syncthreads();
    return r;
}
__device__ __forceinline__ float fast_tanh(float x) {
    float y;
    asm("tanh.approx.f32 %0, %1;" : "=f"(y) : "f"(x));
    return y;
}
// packed fp32x2 FMA (FFMA2)
__device__ __forceinline__ ULL pk2(float lo, float hi) {
    ULL r; asm("mov.b64 %0, {%1, %2};" : "=l"(r) : "f"(lo), "f"(hi)); return r;
}
__device__ __forceinline__ void ffma2(ULL& d, ULL a, ULL b) {
    asm("fma.rn.f32x2 %0, %1, %2, %0;" : "+l"(d) : "l"(a), "l"(b));
}
__device__ __forceinline__ float fold2(ULL a) {
    float lo, hi; asm("mov.b64 {%0, %1}, %2;" : "=f"(lo), "=f"(hi) : "l"(a));
    return lo + hi;
}

// 16-row x 2-col GEMM tile core (k-paired FFMA2), K = 4*K4.
template<int K4, class F>
__device__ __forceinline__ void gemm16x2(const ulonglong2* __restrict__ sn,
                                         const float* __restrict__ wbase, int wstride,
                                         F emit) {
    ULL acc0[16], acc1[16];
    #pragma unroll
    for (int r = 0; r < 16; r++) { acc0[r] = 0ull; acc1[r] = 0ull; }
    #pragma unroll 2
    for (int k4 = 0; k4 < K4; k4++) {
        const float* wp = wbase + (k4 * 4) * wstride;
        float2 v0 = __ldg((const float2*)(wp));
        float2 v1 = __ldg((const float2*)(wp + wstride));
        float2 v2 = __ldg((const float2*)(wp + 2 * wstride));
        float2 v3 = __ldg((const float2*)(wp + 3 * wstride));
        ULL w01a = pk2(v0.x, v1.x), w01b = pk2(v0.y, v1.y);
        ULL w23a = pk2(v2.x, v3.x), w23b = pk2(v2.y, v3.y);
        #pragma unroll
        for (int r = 0; r < 16; r++) {
            ulonglong2 x = sn[r * K4 + k4];
            ffma2(acc0[r], x.x, w01a);
            ffma2(acc0[r], x.y, w23a);
            ffma2(acc1[r], x.x, w01b);
            ffma2(acc1[r], x.y, w23b);
        }
    }
    #pragma unroll
    for (int r = 0; r < 16; r++) emit(r, fold2(acc0[r]), fold2(acc1[r]));
}

// =====================================================================
// L1 FRONT: h+el/er | drug score | Sdx static | edge count | A-CSR scan
// =====================================================================
__global__ void k_front(const float* __restrict__ dxEmb, const float* __restrict__ extra,
                        const float* __restrict__ W, const float* __restrict__ al,
                        const float* __restrict__ ar,
                        const float* __restrict__ drEmb, const float* __restrict__ drEmb2,
                        const float* __restrict__ attnW,
                        const int* __restrict__ edst,
                        const float* __restrict__ A) {
    __shared__ __align__(16) float4 sn4[32 * 64];   // 32KB
    __shared__ float pel[32][2];
    __shared__ float per[32][2];
    const int bid = blockIdx.x, tid = threadIdx.x;
    const int lane = tid & 31, wp2 = (tid >> 5) & 1;
    const int t64 = tid & 63, rowgrp = tid >> 6;
    const int c0 = 2 * t64;

    if (bid < B_H) {
        // ---- h = nodes @ gat_W (32 rows) + fused el/er ----
        const int r0 = bid * 32;
        for (int i = tid; i < 32 * 32; i += 128) {
            int rr = i >> 5, c4 = i & 31;
            int row = r0 + rr;
            float4 v = make_float4(0.f, 0.f, 0.f, 0.f);
            if (row < NNODE)
                v = (row < DXV) ? ((const float4*)dxEmb)[row * 32 + c4]
                                : ((const float4*)extra)[(row - DXV) * 32 + c4];
            sn4[i] = v;
        }
        __syncthreads();
        float2 al2 = __ldg((const float2*)(al + c0));
        float2 ar2 = __ldg((const float2*)(ar + c0));
        const ulonglong2* sn = (const ulonglong2*)sn4 + rowgrp * 16 * 32;
        gemm16x2<32>(sn, W + c0, Dm,
            [&](int rr, float v0, float v1) {
                int row = r0 + rowgrp * 16 + rr;
                if (row < NNODE) {
                    g_h[(long)row * Dm + c0]     = v0;
                    g_h[(long)row * Dm + c0 + 1] = v1;
                }
                float p = warpSum(v0 * al2.x + v1 * al2.y);
                float q = warpSum(v0 * ar2.x + v1 * ar2.y);
                if (lane == 0) {
                    pel[rowgrp * 16 + rr][wp2] = p;
                    per[rowgrp * 16 + rr][wp2] = q;
                }
            });
        __syncthreads();
        if (tid < 32) {
            int row = r0 + tid;
            if (row < NNODE) g_el[row] = pel[tid][0] + pel[tid][1];
        } else if (tid < 64) {
            int rr = tid - 32, row = r0 + rr;
            if (row < NNODE) g_er[row] = per[rr][0] + per[rr][1];
        }
    } else if (bid < B_H + B_DR) {
        // ---- drug score (K=256): drEmb@W[0:128] + drEmb2@W[128:256] ----
        const int r0 = (bid - B_H) * 32;
        for (int i = tid; i < 32 * 64; i += 128) {
            int rr = i >> 6, c4 = i & 63;
            int row = r0 + rr;
            float4 v = make_float4(0.f, 0.f, 0.f, 0.f);
            if (row < DRV)
                v = (c4 < 32) ? ((const float4*)drEmb)[row * 32 + c4]
                              : ((const float4*)drEmb2)[row * 32 + (c4 - 32)];
            sn4[i] = v;
        }
        __syncthreads();
        const ulonglong2* sn = (const ulonglong2*)sn4 + rowgrp * 16 * 64;
        gemm16x2<64>(sn, attnW + c0, Dm,
            [&](int rr, float v0, float v1) {
                int row = r0 + rowgrp * 16 + rr;
                if (row < DRV) {
                    g_Sdrug[(long)row * Dm + c0]     = v0;
                    g_Sdrug[(long)row * Dm + c0 + 1] = v1;
                }
            });
    } else if (bid < B_H + B_DR + B_SDX) {
        // ---- Sdx static half (K=128): dxEmb @ attnW[0:128] ----
        const int r0 = (bid - B_H - B_DR) * 32;
        for (int i = tid; i < 32 * 32; i += 128) {
            int rr = i >> 5, c4 = i & 31;
            int row = r0 + rr;
            sn4[i] = (row < DXV) ? ((const float4*)dxEmb)[row * 32 + c4]
                                 : make_float4(0.f, 0.f, 0.f, 0.f);
        }
        __syncthreads();
        const ulonglong2* sn = (const ulonglong2*)sn4 + rowgrp * 16 * 32;
        gemm16x2<32>(sn, attnW + c0, Dm,
            [&](int rr, float v0, float v1) {
                int row = r0 + rowgrp * 16 + rr;
                if (row < DXV) {
                    g_SdxA[(long)row * Dm + c0]     = v0;
                    g_SdxA[(long)row * Dm + c0 + 1] = v1;
                }
            });
    } else if (bid < B_H + B_DR + B_SDX + B_CNT) {
        // ---- edge count ----
        int cb = bid - B_H - B_DR - B_SDX;
        #pragma unroll
        for (int q = 0; q < 4; q++) {
            int i = cb * 512 + q * 128 + tid;
            if (i < ECNT) {
                int d = edst[i];
                if (d < DXV) g_rank[i] = atomicAdd(&g_count[d], 1);
            }
        }
    } else {
        // ---- A-CSR scan: find nonzeros of dx_to_ancestor ----
        // Slots assigned by atomic rank (order nondeterministic); consumer
        // canonical-sorts by ancestor idx => deterministic output.
        int cb = bid - B_H - B_DR - B_SDX - B_CNT;
        const float4* A4 = (const float4*)A;
        #pragma unroll
        for (int q = 0; q < 4; q++) {
            int f4 = cb * 512 + q * 128 + tid;
            if (f4 < NF4) {
                float4 v = __ldg(A4 + f4);
                if (v.x != 0.f || v.y != 0.f || v.z != 0.f || v.w != 0.f) {
                    int row = f4 / (NANC / 4);
                    int cbase = (f4 - row * (NANC / 4)) * 4;
                    float vv[4] = {v.x, v.y, v.z, v.w};
                    #pragma unroll
                    for (int c = 0; c < 4; c++) {
                        if (vv[c] != 0.f) {
                            int r = atomicAdd(&g_anccnt[row], 1);
                            if (r < ANCCAP) {
                                g_ancval[row * ANCCAP + r] = vv[c];
                                g_ancidx[row * ANCCAP + r] = cbase + c;
                            }
                        }
                    }
                }
            }
        }
    }
}

// =====================================================================
// L2: single-block two-level exclusive scan (1024 thr, 10 elems each)
// =====================================================================
__global__ void k_scan() {
    __shared__ int wsum[32];
    const int tid = threadIdx.x, l = tid & 31, w = tid >> 5;
    int pre[10];
    int s = 0;
    #pragma unroll
    for (int k = 0; k < 10; k++) {
        int idx = tid * 10 + k;
        int v = (idx < DXV) ? g_count[idx] : 0;
        pre[k] = s; s += v;
    }
    int x = s;
    #pragma unroll
    for (int o = 1; o < 32; o <<= 1) {
        int y = __shfl_up_sync(0xffffffffu, x, o);
        if (l >= o) x += y;
    }
    if (l == 31) wsum[w] = x;
    __syncthreads();
    if (w == 0) {
        int ws = wsum[l];
        #pragma unroll
        for (int o = 1; o < 32; o <<= 1) {
            int y = __shfl_up_sync(0xffffffffu, ws, o);
            if (l >= o) ws += y;
        }
        wsum[l] = ws;
    }
    __syncthreads();
    int texcl = ((w > 0) ? wsum[w - 1] : 0) + x - s;
    #pragma unroll
    for (int k = 0; k < 10; k++) {
        int idx = tid * 10 + k;
        if (idx < DXV) g_rowoff[idx] = texcl + pre[k];
    }
    if (tid == 0) g_rowoff[DXV] = wsum[31];
}

// =====================================================================
// L3: atomic-free scatter + re-zero counts for next call
// =====================================================================
__global__ void k_scatter(const int* __restrict__ dst) {
    int i = blockIdx.x * blockDim.x + threadIdx.x;
    if (i < ECNT) {
        int d = dst[i];
        if (d < DXV) g_eid[g_rowoff[d] + g_rank[i]] = i;
    }
    if (i < DXV) g_count[i] = 0;
}

// =====================================================================
// L4 (profiled slot): FUSED GAT-aggregate + classEmb (prebuilt anc CSR)
//   dxALLonto[d] = softmax-agg(h over in-edges of d) + L2norm(A[d] @ S)
// =====================================================================
__global__ void k_aggCE(const int* __restrict__ esrc, const float* __restrict__ S) {
    const int d = blockIdx.x, tid = threadIdx.x;
    const int lane = tid & 31, w = tid >> 5;
    __shared__ int   sid[MAXDEG];
    __shared__ int   ssrc[MAXDEG];
    __shared__ float sw[MAXDEG];
    __shared__ float shred[4];
    __shared__ float spart[4][128];
    __shared__ float sVr[ANCCAP];
    __shared__ int   sIr[ANCCAP];
    __shared__ float sV[ANCCAP];
    __shared__ int   sI[ANCCAP];

    // anc CSR for this row (built by k_front). NOTE: the count reset happens
    // AFTER the barrier below — every warp must read cnt before tid0 zeroes it
    // (read-then-reset race caused OOB via uninitialized sI in R12).
    int cnt = g_anccnt[d];
    if (cnt > ANCCAP) cnt = ANCCAP;
    if (tid < cnt) {
        sVr[tid] = g_ancval[d * ANCCAP + tid];
        sIr[tid] = g_ancidx[d * ANCCAP + tid];
    }

    // edge CSR
    int base = g_rowoff[d];
    int n = g_rowoff[d + 1] - base;
    if (n > MAXDEG) n = MAXDEG;
    for (int j = tid; j < n; j += 128) sid[j] = g_eid[base + j];
    __syncthreads();
    if (tid == 0) g_anccnt[d] = 0;   // safe: all warps have read cnt

    // deterministic sorts: edges by edge id; anc entries by ancestor idx
    for (int j = tid; j < n; j += 128) {
        int id = sid[j];
        int rk = 0;
        for (int k = 0; k < n; k++) rk += (sid[k] < id);
        ssrc[rk] = id;
    }
    if (tid < cnt) {
        int my = sIr[tid];
        int rk = 0;
        for (int k = 0; k < cnt; k++) rk += (sIr[k] < my);
        sV[rk] = sVr[tid];
        sI[rk] = my;
    }
    __syncthreads();

    float er_d = g_er[d];
    for (int j = tid; j < n; j += 128) {
        int s = esrc[ssrc[j]];
        float x = g_el[s] + er_d;
        sw[j] = (x >= 0.f) ? x : 0.2f * x;
        ssrc[j] = s;
    }
    __syncthreads();
    float m = -1e30f;
    for (int j = tid; j < n; j += 128) m = fmaxf(m, sw[j]);
    m = blockMax128(m, shred);
    float ps = 0.f;
    for (int j = tid; j < n; j += 128) {
        float ww = __expf(sw[j] - m);
        sw[j] = ww;
        ps += ww;
    }
    float inv = 1.f / (blockSum128(ps, shred) + 1e-9f);

    // classEmb gather (ascending ancestor order)
    float ce = 0.f;
    #pragma unroll 2
    for (int j = 0; j < cnt; j++)
        ce += sV[j] * __ldg(S + sI[j] * Dm + tid);

    // warp-split aggregate: warp w takes j ≡ w (mod 4); fixed order => deterministic
    float a0 = 0.f, a1 = 0.f, a2 = 0.f, a3 = 0.f;
    #pragma unroll 2
    for (int j = w; j < n; j += 4) {
        float wt = sw[j];
        const float* hp = g_h + (long)ssrc[j] * Dm + lane;
        a0 += wt * hp[0];
        a1 += wt * hp[32];
        a2 += wt * hp[64];
        a3 += wt * hp[96];
    }
    spart[w][lane]      = a0;
    spart[w][lane + 32] = a1;
    spart[w][lane + 64] = a2;
    spart[w][lane + 96] = a3;

    // classEmb L2 norm (blockSum has its own syncs; also covers spart)
    float ss = blockSum128(ce * ce, shred);
    float cen = ce / (sqrtf(ss) + 1e-12f);

    float acc = spart[0][tid] + spart[1][tid] + spart[2][tid] + spart[3][tid];
    g_dxALLonto[(long)d * Dm + tid] = acc * inv + cen;
}

// =====================================================================
// L5: Sdx = SdxA + dxALLonto @ attnW[128:256]   (K=128 only)
// =====================================================================
__global__ void k_scoreDx2(const float* __restrict__ attnW) {
    __shared__ __align__(16) float4 sn4[32 * 32];   // 16KB
    const int tid = threadIdx.x;
    const int t64 = tid & 63, rowgrp = tid >> 6;
    const int c0 = 2 * t64;
    const int r0 = blockIdx.x * 32;
    for (int i = tid; i < 32 * 32; i += 128) {
        int rr = i >> 5, c4 = i & 31;
        int row = r0 + rr;
        sn4[i] = (row < DXV) ? ((const float4*)g_dxALLonto)[row * 32 + c4]
                             : make_float4(0.f, 0.f, 0.f, 0.f);
    }
    __syncthreads();
    const ulonglong2* sn = (const ulonglong2*)sn4 + rowgrp * 16 * 32;
    gemm16x2<32>(sn, attnW + Dm * Dm + c0, Dm,
        [&](int rr, float v0, float v1) {
            int row = r0 + rowgrp * 16 + rr;
            if (row < DXV) {
                float2 sa = __ldg((const float2*)(g_SdxA + (long)row * Dm + c0));
                g_Sdx[(long)row * Dm + c0]     = v0 + sa.x;
                g_Sdx[(long)row * Dm + c0 + 1] = v1 + sa.y;
            }
        });
}

// =====================================================================
// L6: per-visit attention
// =====================================================================
__global__ void k_visit(const int* __restrict__ dxseqs, const int* __restrict__ drugseqs,
                        const float* __restrict__ dxEmb, const float* __restrict__ drEmb,
                        const float* __restrict__ drEmb2, const float* __restrict__ attnW,
                        const float* __restrict__ attnB, const float* __restrict__ combW,
                        const float* __restrict__ combB) {
    const int bv = blockIdx.x, tid = threadIdx.x;
    __shared__ int   sh_idx[NCODE];
    __shared__ __align__(16) float s_u[256];
    __shared__ float s_up[Dm];
    __shared__ float s_sc[NCODE];
    __shared__ float s_alpha[NCODE];
    __shared__ float shred[4];

    if (tid < NDX)        sh_idx[tid] = dxseqs[bv * NDX + tid];
    else if (tid < NCODE) sh_idx[tid] = drugseqs[bv * NDX + (tid - NDX)];
    __syncthreads();

    float u0 = 0.f, u1 = 0.f;
    #pragma unroll 4
    for (int k = 0; k < NCODE; k++) {
        int id = sh_idx[k];
        const float *p0, *p1;
        if (k < NDX) { p0 = dxEmb + (long)id * Dm; p1 = g_dxALLonto + (long)id * Dm; }
        else         { p0 = drEmb + (long)id * Dm; p1 = drEmb2 + (long)id * Dm; }
        u0 += p0[tid];
        u1 += p1[tid];
    }
    s_u[tid] = u0 * (1.f / NCODE);
    s_u[Dm + tid] = u1 * (1.f / NCODE);
    __syncthreads();

    {   // u_part = u @ attnW[256:512] + attn_b   (k-paired FFMA2)
        const ULL* su64 = (const ULL*)s_u;
        ULL up2 = 0ull;
        #pragma unroll 4
        for (int k2 = 0; k2 < 128; k2++) {
            ULL wv = pk2(__ldg(attnW + (256 + 2 * k2) * Dm + tid),
                         __ldg(attnW + (257 + 2 * k2) * Dm + tid));
            ffma2(up2, su64[k2], wv);
        }
        s_up[tid] = __ldg(attnB + tid) + fold2(up2);
    }
    __syncthreads();

    const int w = tid >> 5, lane = tid & 31;
    const float cb = __ldg(combB);
    for (int k = w; k < NCODE; k += 4) {
        int id = sh_idx[k];
        const float* base = (k < NDX) ? (g_Sdx + (long)id * Dm) : (g_Sdrug + (long)id * Dm);
        float t = 0.f;
        #pragma unroll
        for (int q = 0; q < 4; q++) {
            int dcol = lane + 32 * q;
            t += fast_tanh(base[dcol] + s_up[dcol]) * __ldg(combW + dcol);
        }
        t = warpSum(t);
        if (lane == 0) s_sc[k] = t + cb;
    }
    __syncthreads();

    float sv = (tid < NCODE) ? s_sc[tid] : -1e30f;
    float m = blockMax128(sv, shred);
    float e = (tid < NCODE) ? __expf(sv - m) : 0.f;
    float Z = blockSum128(e, shred);
    if (tid < NCODE) s_alpha[tid] = e / Z;
    __syncthreads();

    float v0 = 0.f, v1 = 0.f;
    #pragma unroll 4
    for (int k = 0; k < NCODE; k++) {
        float a = s_alpha[k];
        int id = sh_idx[k];
        const float *p0, *p1;
        if (k < NDX) { p0 = dxEmb + (long)id * Dm; p1 = g_dxALLonto + (long)id * Dm; }
        else         { p0 = drEmb + (long)id * Dm; p1 = drEmb2 + (long)id * Dm; }
        v0 += a * p0[tid];
        v1 += a * p1[tid];
    }
    g_visit[bv * 256 + tid] = v0;
    g_visit[bv * 256 + Dm + tid] = v1;
}

// =====================================================================
// L7: out = sigmoid(visit @ dp_W + dp_b)   (32 rows x 128 cols per block)
// =====================================================================
__global__ void k_dp(const float* __restrict__ dpW, const float* __restrict__ dpB,
                     float* __restrict__ out) {
    __shared__ __align__(16) float4 sv4[32 * 64];   // 32KB
    const int tid = threadIdx.x;
    const int t64 = tid & 63, rowgrp = tid >> 6;
    const int c0 = blockIdx.x * 128 + 2 * t64;
    const int r0 = blockIdx.y * 32;
    for (int i = tid; i < 32 * 64; i += 128)
        sv4[i] = ((const float4*)g_visit)[r0 * 64 + i];
    __syncthreads();
    if (c0 >= LBL) return;   // LBL even -> pairs never straddle
    float2 b2 = __ldg((const float2*)(dpB + c0));
    const ulonglong2* sn = (const ulonglong2*)sv4 + rowgrp * 16 * 64;
    gemm16x2<64>(sn, dpW + c0, LBL,
        [&](int rr, float v0, float v1) {
            int row = r0 + rowgrp * 16 + rr;
            out[(long)row * LBL + c0]     = 1.f / (1.f + __expf(-(v0 + b2.x)));
            out[(long)row * LBL + c0 + 1] = 1.f / (1.f + __expf(-(v1 + b2.y)));
        });
}

// ---------------- launcher ----------------
extern "C" void kernel_launch(void* const* d_in, const int* in_sizes, int n_in,
                              void* d_out, int out_size) {
    const int*   dxseqs  = (const int*)d_in[0];
    const int*   drugseqs= (const int*)d_in[1];
    const int*   esrc    = (const int*)d_in[2];
    const int*   edst    = (const int*)d_in[3];
    const float* dx2anc  = (const float*)d_in[4];
    const float* dxEmb   = (const float*)d_in[5];
    const float* drEmb   = (const float*)d_in[6];
    const float* drEmb2  = (const float*)d_in[7];
    const float* extra   = (const float*)d_in[8];
    const float* S       = (const float*)d_in[9];
    const float* gatW    = (const float*)d_in[10];
    const float* gal     = (const float*)d_in[11];
    const float* gar     = (const float*)d_in[12];
    const float* attnW   = (const float*)d_in[13];
    const float* attnB   = (const float*)d_in[14];
    const float* combW   = (const float*)d_in[15];
    const float* combB   = (const float*)d_in[16];
    const float* dpW     = (const float*)d_in[17];
    const float* dpB     = (const float*)d_in[18];
    float*       out     = (float*)d_out;

    // k_aggCE lands in profiled slot 4.
    k_front<<<B_H + B_DR + B_SDX + B_CNT + B_ASC, 128>>>(dxEmb, extra, gatW, gal, gar,
                                                         drEmb, drEmb2, attnW, edst, dx2anc);
    k_scan<<<1, 1024>>>();
    k_scatter<<<(ECNT + 255) / 256, 256>>>(edst);
    k_aggCE<<<DXV, 128>>>(esrc, S);
    k_scoreDx2<<<B_SDX, 128>>>(attnW);
    k_visit<<<NBV, 128>>>(dxseqs, drugseqs, dxEmb, drEmb, drEmb2,
                          attnW, attnB, combW, combB);
    k_dp<<<dim3((LBL + 127) / 128, NBV / 32), 128>>>(dpW, dpB, out);
}

// round 14
// speedup vs baseline: 1.1983x; 1.1983x over previous
#include <cuda_runtime.h>
#include <math.h>

// ---------------- problem constants ----------------
#define DXV   10000
#define DRV   5000
#define NANC  2000
#define NNODE 18000     // DXV + SPLIT*NANC
#define Dm    128
#define ECNT  200000
#define NBV   640       // B*V
#define NCODE 80
#define NDX   40
#define LBL   2000
#define MAXDEG 192
#define ANCCAP 128      // per-row nonzero capacity (mean ~20)

#define B_H    563      // ceil(18000/32)
#define B_DR   157      // ceil(5000/32)
#define B_SDX  313      // ceil(10000/32)
#define B_CNT  391      // ceil(200000/512)

typedef unsigned long long ULL;

// ---------------- scratch ----------------
__device__ float g_h[NNODE * Dm];
__device__ float g_el[NNODE];
__device__ float g_er[NNODE];
__device__ int   g_count[DXV];      // zero at load; re-zeroed by k_scatter each call
__device__ int   g_rowoff[DXV + 1];
__device__ int   g_rank[ECNT];
__device__ int   g_eid[ECNT];
__device__ float g_dxALLonto[DXV * Dm];
__device__ float g_SdxA[DXV * Dm];  // static half: dxEmb @ attnW[0:128]
__device__ float g_Sdx[DXV * Dm];
__device__ float g_Sdrug[DRV * Dm];
__device__ float g_visit[NBV * 2 * Dm];

// ---------------- helpers ----------------
__device__ __forceinline__ float warpSum(float x) {
    #pragma unroll
    for (int o = 16; o; o >>= 1) x += __shfl_xor_sync(0xffffffffu, x, o);
    return x;
}
__device__ __forceinline__ float warpMax(float x) {
    #pragma unroll
    for (int o = 16; o; o >>= 1) x = fmaxf(x, __shfl_xor_sync(0xffffffffu, x, o));
    return x;
}
__device__ __forceinline__ float blockSum128(float x, float* sh) {
    int w = threadIdx.x >> 5, l = threadIdx.x & 31;
    x = warpSum(x);
    if (l == 0) sh[w] = x;
    __syncthreads();
    float r = sh[0] + sh[1] + sh[2] + sh[3];
    __syncthreads();
    return r;
}
__device__ __forceinline__ float blockMax128(float x, float* sh) {
    int w = threadIdx.x >> 5, l = threadIdx.x & 31;
    x = warpMax(x);
    if (l == 0) sh[w] = x;
    __syncthreads();
    float r = fmaxf(fmaxf(sh[0], sh[1]), fmaxf(sh[2], sh[3]));
    __syncthreads();
    return r;
}
__device__ __forceinline__ float fast_tanh(float x) {
    float y;
    asm("tanh.approx.f32 %0, %1;" : "=f"(y) : "f"(x));
    return y;
}
// packed fp32x2 FMA (FFMA2)
__device__ __forceinline__ ULL pk2(float lo, float hi) {
    ULL r; asm("mov.b64 %0, {%1, %2};" : "=l"(r) : "f"(lo), "f"(hi)); return r;
}
__device__ __forceinline__ void ffma2(ULL& d, ULL a, ULL b) {
    asm("fma.rn.f32x2 %0, %1, %2, %0;" : "+l"(d) : "l"(a), "l"(b));
}
__device__ __forceinline__ float fold2(ULL a) {
    float lo, hi; asm("mov.b64 {%0, %1}, %2;" : "=f"(lo), "=f"(hi) : "l"(a));
    return lo + hi;
}

// 16-row x 2-col GEMM tile core (k-paired FFMA2), K = 4*K4.
template<int K4, class F>
__device__ __forceinline__ void gemm16x2(const ulonglong2* __restrict__ sn,
                                         const float* __restrict__ wbase, int wstride,
                                         F emit) {
    ULL acc0[16], acc1[16];
    #pragma unroll
    for (int r = 0; r < 16; r++) { acc0[r] = 0ull; acc1[r] = 0ull; }
    #pragma unroll 2
    for (int k4 = 0; k4 < K4; k4++) {
        const float* wp = wbase + (k4 * 4) * wstride;
        float2 v0 = __ldg((const float2*)(wp));
        float2 v1 = __ldg((const float2*)(wp + wstride));
        float2 v2 = __ldg((const float2*)(wp + 2 * wstride));
        float2 v3 = __ldg((const float2*)(wp + 3 * wstride));
        ULL w01a = pk2(v0.x, v1.x), w01b = pk2(v0.y, v1.y);
        ULL w23a = pk2(v2.x, v3.x), w23b = pk2(v2.y, v3.y);
        #pragma unroll
        for (int r = 0; r < 16; r++) {
            ulonglong2 x = sn[r * K4 + k4];
            ffma2(acc0[r], x.x, w01a);
            ffma2(acc0[r], x.y, w23a);
            ffma2(acc1[r], x.x, w01b);
            ffma2(acc1[r], x.y, w23b);
        }
    }
    #pragma unroll
    for (int r = 0; r < 16; r++) emit(r, fold2(acc0[r]), fold2(acc1[r]));
}

// =====================================================================
// L1 FRONT: h+el/er | drug score | Sdx static | edge count
// =====================================================================
__global__ void k_front(const float* __restrict__ dxEmb, const float* __restrict__ extra,
                        const float* __restrict__ W, const float* __restrict__ al,
                        const float* __restrict__ ar,
                        const float* __restrict__ drEmb, const float* __restrict__ drEmb2,
                        const float* __restrict__ attnW,
                        const int* __restrict__ edst) {
    __shared__ __align__(16) float4 sn4[32 * 64];   // 32KB
    __shared__ float pel[32][2];
    __shared__ float per[32][2];
    const int bid = blockIdx.x, tid = threadIdx.x;
    const int lane = tid & 31, wp2 = (tid >> 5) & 1;
    const int t64 = tid & 63, rowgrp = tid >> 6;
    const int c0 = 2 * t64;

    if (bid < B_H) {
        // ---- h = nodes @ gat_W (32 rows) + fused el/er ----
        const int r0 = bid * 32;
        for (int i = tid; i < 32 * 32; i += 128) {
            int rr = i >> 5, c4 = i & 31;
            int row = r0 + rr;
            float4 v = make_float4(0.f, 0.f, 0.f, 0.f);
            if (row < NNODE)
                v = (row < DXV) ? ((const float4*)dxEmb)[row * 32 + c4]
                                : ((const float4*)extra)[(row - DXV) * 32 + c4];
            sn4[i] = v;
        }
        __syncthreads();
        float2 al2 = __ldg((const float2*)(al + c0));
        float2 ar2 = __ldg((const float2*)(ar + c0));
        const ulonglong2* sn = (const ulonglong2*)sn4 + rowgrp * 16 * 32;
        gemm16x2<32>(sn, W + c0, Dm,
            [&](int rr, float v0, float v1) {
                int row = r0 + rowgrp * 16 + rr;
                if (row < NNODE) {
                    g_h[(long)row * Dm + c0]     = v0;
                    g_h[(long)row * Dm + c0 + 1] = v1;
                }
                float p = warpSum(v0 * al2.x + v1 * al2.y);
                float q = warpSum(v0 * ar2.x + v1 * ar2.y);
                if (lane == 0) {
                    pel[rowgrp * 16 + rr][wp2] = p;
                    per[rowgrp * 16 + rr][wp2] = q;
                }
            });
        __syncthreads();
        if (tid < 32) {
            int row = r0 + tid;
            if (row < NNODE) g_el[row] = pel[tid][0] + pel[tid][1];
        } else if (tid < 64) {
            int rr = tid - 32, row = r0 + rr;
            if (row < NNODE) g_er[row] = per[rr][0] + per[rr][1];
        }
    } else if (bid < B_H + B_DR) {
        // ---- drug score (K=256): drEmb@W[0:128] + drEmb2@W[128:256] ----
        const int r0 = (bid - B_H) * 32;
        for (int i = tid; i < 32 * 64; i += 128) {
            int rr = i >> 6, c4 = i & 63;
            int row = r0 + rr;
            float4 v = make_float4(0.f, 0.f, 0.f, 0.f);
            if (row < DRV)
                v = (c4 < 32) ? ((const float4*)drEmb)[row * 32 + c4]
                              : ((const float4*)drEmb2)[row * 32 + (c4 - 32)];
            sn4[i] = v;
        }
        __syncthreads();
        const ulonglong2* sn = (const ulonglong2*)sn4 + rowgrp * 16 * 64;
        gemm16x2<64>(sn, attnW + c0, Dm,
            [&](int rr, float v0, float v1) {
                int row = r0 + rowgrp * 16 + rr;
                if (row < DRV) {
                    g_Sdrug[(long)row * Dm + c0]     = v0;
                    g_Sdrug[(long)row * Dm + c0 + 1] = v1;
                }
            });
    } else if (bid < B_H + B_DR + B_SDX) {
        // ---- Sdx static half (K=128): dxEmb @ attnW[0:128] ----
        const int r0 = (bid - B_H - B_DR) * 32;
        for (int i = tid; i < 32 * 32; i += 128) {
            int rr = i >> 5, c4 = i & 31;
            int row = r0 + rr;
            sn4[i] = (row < DXV) ? ((const float4*)dxEmb)[row * 32 + c4]
                                 : make_float4(0.f, 0.f, 0.f, 0.f);
        }
        __syncthreads();
        const ulonglong2* sn = (const ulonglong2*)sn4 + rowgrp * 16 * 32;
        gemm16x2<32>(sn, attnW + c0, Dm,
            [&](int rr, float v0, float v1) {
                int row = r0 + rowgrp * 16 + rr;
                if (row < DXV) {
                    g_SdxA[(long)row * Dm + c0]     = v0;
                    g_SdxA[(long)row * Dm + c0 + 1] = v1;
                }
            });
    } else {
        // ---- edge count ----
        int cb = bid - B_H - B_DR - B_SDX;
        #pragma unroll
        for (int q = 0; q < 4; q++) {
            int i = cb * 512 + q * 128 + tid;
            if (i < ECNT) {
                int d = edst[i];
                if (d < DXV) g_rank[i] = atomicAdd(&g_count[d], 1);
            }
        }
    }
}

// =====================================================================
// L2: single-block two-level exclusive scan (1024 thr, 10 elems each)
// =====================================================================
__global__ void k_scan() {
    __shared__ int wsum[32];
    const int tid = threadIdx.x, l = tid & 31, w = tid >> 5;
    int pre[10];
    int s = 0;
    #pragma unroll
    for (int k = 0; k < 10; k++) {
        int idx = tid * 10 + k;
        int v = (idx < DXV) ? g_count[idx] : 0;
        pre[k] = s; s += v;
    }
    int x = s;
    #pragma unroll
    for (int o = 1; o < 32; o <<= 1) {
        int y = __shfl_up_sync(0xffffffffu, x, o);
        if (l >= o) x += y;
    }
    if (l == 31) wsum[w] = x;
    __syncthreads();
    if (w == 0) {
        int ws = wsum[l];
        #pragma unroll
        for (int o = 1; o < 32; o <<= 1) {
            int y = __shfl_up_sync(0xffffffffu, ws, o);
            if (l >= o) ws += y;
        }
        wsum[l] = ws;
    }
    __syncthreads();
    int texcl = ((w > 0) ? wsum[w - 1] : 0) + x - s;
    #pragma unroll
    for (int k = 0; k < 10; k++) {
        int idx = tid * 10 + k;
        if (idx < DXV) g_rowoff[idx] = texcl + pre[k];
    }
    if (tid == 0) g_rowoff[DXV] = wsum[31];
}

// =====================================================================
// L3: atomic-free scatter + re-zero counts for next call
// =====================================================================
__global__ void k_scatter(const int* __restrict__ dst) {
    int i = blockIdx.x * blockDim.x + threadIdx.x;
    if (i < ECNT) {
        int d = dst[i];
        if (d < DXV) g_eid[g_rowoff[d] + g_rank[i]] = i;
    }
    if (i < DXV) g_count[i] = 0;
}

// =====================================================================
// L4 (profiled slot): FUSED GAT-aggregate + classEmb per dx row
//   dxALLonto[d] = softmax-agg(h over in-edges of d) + L2norm(A[d] @ S)
//   A-row nonzeros found via shared-atomic append (order laundered by
//   canonical index sort => deterministic).
// =====================================================================
__global__ void k_aggCE(const int* __restrict__ esrc,
                        const float* __restrict__ A, const float* __restrict__ S) {
    const int d = blockIdx.x, tid = threadIdx.x;
    const int lane = tid & 31, w = tid >> 5;
    __shared__ int   sid[MAXDEG];
    __shared__ int   ssrc[MAXDEG];
    __shared__ float sw[MAXDEG];
    __shared__ float shred[4];
    __shared__ float spart[4][128];
    __shared__ float sVr[ANCCAP];
    __shared__ int   sIr[ANCCAP];
    __shared__ float sV[ANCCAP];
    __shared__ int   sI[ANCCAP];
    __shared__ int   s_cnt;

    // --- issue the A-row loads first (fly under the CSR phase) ---
    const float4* r4 = (const float4*)(A + (long)d * NANC);
    float4 va[4];
    #pragma unroll
    for (int q = 0; q < 4; q++) {
        int f4 = tid * 4 + q;
        va[q] = (f4 < NANC / 4) ? __ldg(r4 + f4) : make_float4(0.f, 0.f, 0.f, 0.f);
    }
    if (tid == 0) s_cnt = 0;

    // --- edge CSR load ---
    int base = g_rowoff[d];
    int n = g_rowoff[d + 1] - base;
    if (n > MAXDEG) n = MAXDEG;
    for (int j = tid; j < n; j += 128) sid[j] = g_eid[base + j];
    __syncthreads();

    // edges: deterministic ascending edge-id order via rank sort
    for (int j = tid; j < n; j += 128) {
        int id = sid[j];
        int rk = 0;
        for (int k = 0; k < n; k++) rk += (sid[k] < id);
        ssrc[rk] = id;
    }
    // anc: shared-atomic append of nonzeros (no ballots; ~20 appends/block)
    {
        const float* vf = (const float*)va;
        #pragma unroll
        for (int t = 0; t < 16; t++) {
            float v = vf[t];
            if (v != 0.f) {
                int p = atomicAdd(&s_cnt, 1);
                if (p < ANCCAP) { sVr[p] = v; sIr[p] = tid * 16 + t; }
            }
        }
    }
    __syncthreads();

    int cnt = s_cnt;
    if (cnt > ANCCAP) cnt = ANCCAP;
    // anc canonical sort by ancestor index (unique) => deterministic order
    if (tid < cnt) {
        int my = sIr[tid];
        int rk = 0;
        for (int k = 0; k < cnt; k++) rk += (sIr[k] < my);
        sV[rk] = sVr[tid];
        sI[rk] = my;
    }
    float er_d = g_er[d];
    for (int j = tid; j < n; j += 128) {
        int s = esrc[ssrc[j]];
        float x = g_el[s] + er_d;
        sw[j] = (x >= 0.f) ? x : 0.2f * x;
        ssrc[j] = s;
    }
    __syncthreads();

    float m = -1e30f;
    for (int j = tid; j < n; j += 128) m = fmaxf(m, sw[j]);
    m = blockMax128(m, shred);
    float ps = 0.f;
    for (int j = tid; j < n; j += 128) {
        float ww = __expf(sw[j] - m);
        sw[j] = ww;
        ps += ww;
    }
    float inv = 1.f / (blockSum128(ps, shred) + 1e-9f);

    // classEmb gather (ascending ancestor order)
    float ce = 0.f;
    #pragma unroll 2
    for (int j = 0; j < cnt; j++)
        ce += sV[j] * __ldg(S + sI[j] * Dm + tid);

    // warp-split aggregate: warp w takes j ≡ w (mod 4); fixed order => deterministic
    float a0 = 0.f, a1 = 0.f, a2 = 0.f, a3 = 0.f;
    #pragma unroll 2
    for (int j = w; j < n; j += 4) {
        float wt = sw[j];
        const float* hp = g_h + (long)ssrc[j] * Dm + lane;
        a0 += wt * hp[0];
        a1 += wt * hp[32];
        a2 += wt * hp[64];
        a3 += wt * hp[96];
    }
    spart[w][lane]      = a0;
    spart[w][lane + 32] = a1;
    spart[w][lane + 64] = a2;
    spart[w][lane + 96] = a3;

    // classEmb L2 norm (blockSum has its own syncs; also covers spart)
    float ss = blockSum128(ce * ce, shred);
    float cen = ce / (sqrtf(ss) + 1e-12f);

    float acc = spart[0][tid] + spart[1][tid] + spart[2][tid] + spart[3][tid];
    g_dxALLonto[(long)d * Dm + tid] = acc * inv + cen;
}

// =====================================================================
// L5: Sdx = SdxA + dxALLonto @ attnW[128:256]   (K=128 only)
// =====================================================================
__global__ void k_scoreDx2(const float* __restrict__ attnW) {
    __shared__ __align__(16) float4 sn4[32 * 32];   // 16KB
    const int tid = threadIdx.x;
    const int t64 = tid & 63, rowgrp = tid >> 6;
    const int c0 = 2 * t64;
    const int r0 = blockIdx.x * 32;
    for (int i = tid; i < 32 * 32; i += 128) {
        int rr = i >> 5, c4 = i & 31;
        int row = r0 + rr;
        sn4[i] = (row < DXV) ? ((const float4*)g_dxALLonto)[row * 32 + c4]
                             : make_float4(0.f, 0.f, 0.f, 0.f);
    }
    __syncthreads();
    const ulonglong2* sn = (const ulonglong2*)sn4 + rowgrp * 16 * 32;
    gemm16x2<32>(sn, attnW + Dm * Dm + c0, Dm,
        [&](int rr, float v0, float v1) {
            int row = r0 + rowgrp * 16 + rr;
            if (row < DXV) {
                float2 sa = __ldg((const float2*)(g_SdxA + (long)row * Dm + c0));
                g_Sdx[(long)row * Dm + c0]     = v0 + sa.x;
                g_Sdx[(long)row * Dm + c0 + 1] = v1 + sa.y;
            }
        });
}

// =====================================================================
// L6: per-visit attention
// =====================================================================
__global__ void k_visit(const int* __restrict__ dxseqs, const int* __restrict__ drugseqs,
                        const float* __restrict__ dxEmb, const float* __restrict__ drEmb,
                        const float* __restrict__ drEmb2, const float* __restrict__ attnW,
                        const float* __restrict__ attnB, const float* __restrict__ combW,
                        const float* __restrict__ combB) {
    const int bv = blockIdx.x, tid = threadIdx.x;
    __shared__ int   sh_idx[NCODE];
    __shared__ __align__(16) float s_u[256];
    __shared__ float s_up[Dm];
    __shared__ float s_sc[NCODE];
    __shared__ float s_alpha[NCODE];
    __shared__ float shred[4];

    if (tid < NDX)        sh_idx[tid] = dxseqs[bv * NDX + tid];
    else if (tid < NCODE) sh_idx[tid] = drugseqs[bv * NDX + (tid - NDX)];
    __syncthreads();

    float u0 = 0.f, u1 = 0.f;
    #pragma unroll 4
    for (int k = 0; k < NCODE; k++) {
        int id = sh_idx[k];
        const float *p0, *p1;
        if (k < NDX) { p0 = dxEmb + (long)id * Dm; p1 = g_dxALLonto + (long)id * Dm; }
        else         { p0 = drEmb + (long)id * Dm; p1 = drEmb2 + (long)id * Dm; }
        u0 += p0[tid];
        u1 += p1[tid];
    }
    s_u[tid] = u0 * (1.f / NCODE);
    s_u[Dm + tid] = u1 * (1.f / NCODE);
    __syncthreads();

    {   // u_part = u @ attnW[256:512] + attn_b   (k-paired FFMA2)
        const ULL* su64 = (const ULL*)s_u;
        ULL up2 = 0ull;
        #pragma unroll 4
        for (int k2 = 0; k2 < 128; k2++) {
            ULL wv = pk2(__ldg(attnW + (256 + 2 * k2) * Dm + tid),
                         __ldg(attnW + (257 + 2 * k2) * Dm + tid));
            ffma2(up2, su64[k2], wv);
        }
        s_up[tid] = __ldg(attnB + tid) + fold2(up2);
    }
    __syncthreads();

    const int w = tid >> 5, lane = tid & 31;
    const float cb = __ldg(combB);
    for (int k = w; k < NCODE; k += 4) {
        int id = sh_idx[k];
        const float* base = (k < NDX) ? (g_Sdx + (long)id * Dm) : (g_Sdrug + (long)id * Dm);
        float t = 0.f;
        #pragma unroll
        for (int q = 0; q < 4; q++) {
            int dcol = lane + 32 * q;
            t += fast_tanh(base[dcol] + s_up[dcol]) * __ldg(combW + dcol);
        }
        t = warpSum(t);
        if (lane == 0) s_sc[k] = t + cb;
    }
    __syncthreads();

    float sv = (tid < NCODE) ? s_sc[tid] : -1e30f;
    float m = blockMax128(sv, shred);
    float e = (tid < NCODE) ? __expf(sv - m) : 0.f;
    float Z = blockSum128(e, shred);
    if (tid < NCODE) s_alpha[tid] = e / Z;
    __syncthreads();

    float v0 = 0.f, v1 = 0.f;
    #pragma unroll 4
    for (int k = 0; k < NCODE; k++) {
        float a = s_alpha[k];
        int id = sh_idx[k];
        const float *p0, *p1;
        if (k < NDX) { p0 = dxEmb + (long)id * Dm; p1 = g_dxALLonto + (long)id * Dm; }
        else         { p0 = drEmb + (long)id * Dm; p1 = drEmb2 + (long)id * Dm; }
        v0 += a * p0[tid];
        v1 += a * p1[tid];
    }
    g_visit[bv * 256 + tid] = v0;
    g_visit[bv * 256 + Dm + tid] = v1;
}

// =====================================================================
// L7: out = sigmoid(visit @ dp_W + dp_b)   (32 rows x 128 cols per block)
// =====================================================================
__global__ void k_dp(const float* __restrict__ dpW, const float* __restrict__ dpB,
                     float* __restrict__ out) {
    __shared__ __align__(16) float4 sv4[32 * 64];   // 32KB
    const int tid = threadIdx.x;
    const int t64 = tid & 63, rowgrp = tid >> 6;
    const int c0 = blockIdx.x * 128 + 2 * t64;
    const int r0 = blockIdx.y * 32;
    for (int i = tid; i < 32 * 64; i += 128)
        sv4[i] = ((const float4*)g_visit)[r0 * 64 + i];
    __syncthreads();
    if (c0 >= LBL) return;   // LBL even -> pairs never straddle
    float2 b2 = __ldg((const float2*)(dpB + c0));
    const ulonglong2* sn = (const ulonglong2*)sv4 + rowgrp * 16 * 64;
    gemm16x2<64>(sn, dpW + c0, LBL,
        [&](int rr, float v0, float v1) {
            int row = r0 + rowgrp * 16 + rr;
            out[(long)row * LBL + c0]     = 1.f / (1.f + __expf(-(v0 + b2.x)));
            out[(long)row * LBL + c0 + 1] = 1.f / (1.f + __expf(-(v1 + b2.y)));
        });
}

// ---------------- launcher ----------------
extern "C" void kernel_launch(void* const* d_in, const int* in_sizes, int n_in,
                              void* d_out, int out_size) {
    const int*   dxseqs  = (const int*)d_in[0];
    const int*   drugseqs= (const int*)d_in[1];
    const int*   esrc    = (const int*)d_in[2];
    const int*   edst    = (const int*)d_in[3];
    const float* dx2anc  = (const float*)d_in[4];
    const float* dxEmb   = (const float*)d_in[5];
    const float* drEmb   = (const float*)d_in[6];
    const float* drEmb2  = (const float*)d_in[7];
    const float* extra   = (const float*)d_in[8];
    const float* S       = (const float*)d_in[9];
    const float* gatW    = (const float*)d_in[10];
    const float* gal     = (const float*)d_in[11];
    const float* gar     = (const float*)d_in[12];
    const float* attnW   = (const float*)d_in[13];
    const float* attnB   = (const float*)d_in[14];
    const float* combW   = (const float*)d_in[15];
    const float* combB   = (const float*)d_in[16];
    const float* dpW     = (const float*)d_in[17];
    const float* dpB     = (const float*)d_in[18];
    float*       out     = (float*)d_out;

    // k_aggCE lands in profiled slot 4.
    k_front<<<B_H + B_DR + B_SDX + B_CNT, 128>>>(dxEmb, extra, gatW, gal, gar,
                                                 drEmb, drEmb2, attnW, edst);
    k_scan<<<1, 1024>>>();
    k_scatter<<<(ECNT + 255) / 256, 256>>>(edst);
    k_aggCE<<<DXV, 128>>>(esrc, dx2anc, S);
    k_scoreDx2<<<B_SDX, 128>>>(attnW);
    k_visit<<<NBV, 128>>>(dxseqs, drugseqs, dxEmb, drEmb, drEmb2,
                          attnW, attnB, combW, combB);
    k_dp<<<dim3((LBL + 127) / 128, NBV / 32), 128>>>(dpW, dpB, out);
}

// round 15
// speedup vs baseline: 1.2031x; 1.0040x over previous
#include <cuda_runtime.h>
#include <math.h>

// ---------------- problem constants ----------------
#define DXV   10000
#define DRV   5000
#define NANC  2000
#define NNODE 18000     // DXV + SPLIT*NANC
#define Dm    128
#define ECNT  200000
#define NBV   640       // B*V
#define NCODE 80
#define NDX   40
#define LBL   2000
#define MAXDEG 192
#define ANCCAP 128      // per-row nonzero capacity (mean ~20)

#define B_H    563      // ceil(18000/32)
#define B_DR   157      // ceil(5000/32)
#define B_SDX  313      // ceil(10000/32)
#define B_CNT  391      // ceil(200000/512)
#define ZV4    (DXV * Dm / 4)   // 320000 float4 in g_dxALLonto

typedef unsigned long long ULL;

// ---------------- scratch ----------------
__device__ float g_h[NNODE * Dm];
__device__ float g_el[NNODE];
__device__ float g_er[NNODE];
__device__ int   g_count[DXV];      // zero at load; re-zeroed by k_scatter each call
__device__ int   g_rowoff[DXV + 1];
__device__ int   g_rank[ECNT];
__device__ int   g_eid[ECNT];
__device__ float g_dxALLonto[DXV * Dm];   // zeroed by k_scatter each call
__device__ float g_SdxA[DXV * Dm];  // static half: dxEmb @ attnW[0:128]
__device__ float g_Sdx[DXV * Dm];
__device__ float g_Sdrug[DRV * Dm];
__device__ float g_visit[NBV * 2 * Dm];

// ---------------- helpers ----------------
__device__ __forceinline__ float warpSum(float x) {
    #pragma unroll
    for (int o = 16; o; o >>= 1) x += __shfl_xor_sync(0xffffffffu, x, o);
    return x;
}
__device__ __forceinline__ float warpMax(float x) {
    #pragma unroll
    for (int o = 16; o; o >>= 1) x = fmaxf(x, __shfl_xor_sync(0xffffffffu, x, o));
    return x;
}
__device__ __forceinline__ float blockSum128(float x, float* sh) {
    int w = threadIdx.x >> 5, l = threadIdx.x & 31;
    x = warpSum(x);
    if (l == 0) sh[w] = x;
    __syncthreads();
    float r = sh[0] + sh[1] + sh[2] + sh[3];
    __syncthreads();
    return r;
}
__device__ __forceinline__ float blockMax128(float x, float* sh) {
    int w = threadIdx.x >> 5, l = threadIdx.x & 31;
    x = warpMax(x);
    if (l == 0) sh[w] = x;
    __syncthreads();
    float r = fmaxf(fmaxf(sh[0], sh[1]), fmaxf(sh[2], sh[3]));
    __syncthreads();
    return r;
}
__device__ __forceinline__ float fast_tanh(float x) {
    float y;
    asm("tanh.approx.f32 %0, %1;" : "=f"(y) : "f"(x));
    return y;
}
// packed fp32x2 FMA (FFMA2)
__device__ __forceinline__ ULL pk2(float lo, float hi) {
    ULL r; asm("mov.b64 %0, {%1, %2};" : "=l"(r) : "f"(lo), "f"(hi)); return r;
}
__device__ __forceinline__ void ffma2(ULL& d, ULL a, ULL b) {
    asm("fma.rn.f32x2 %0, %1, %2, %0;" : "+l"(d) : "l"(a), "l"(b));
}
__device__ __forceinline__ float fold2(ULL a) {
    float lo, hi; asm("mov.b64 {%0, %1}, %2;" : "=f"(lo), "=f"(hi) : "l"(a));
    return lo + hi;
}

// 16-row x 2-col GEMM tile core (k-paired FFMA2), K = 4*K4.
template<int K4, class F>
__device__ __forceinline__ void gemm16x2(const ulonglong2* __restrict__ sn,
                                         const float* __restrict__ wbase, int wstride,
                                         F emit) {
    ULL acc0[16], acc1[16];
    #pragma unroll
    for (int r = 0; r < 16; r++) { acc0[r] = 0ull; acc1[r] = 0ull; }
    #pragma unroll 2
    for (int k4 = 0; k4 < K4; k4++) {
        const float* wp = wbase + (k4 * 4) * wstride;
        float2 v0 = __ldg((const float2*)(wp));
        float2 v1 = __ldg((const float2*)(wp + wstride));
        float2 v2 = __ldg((const float2*)(wp + 2 * wstride));
        float2 v3 = __ldg((const float2*)(wp + 3 * wstride));
        ULL w01a = pk2(v0.x, v1.x), w01b = pk2(v0.y, v1.y);
        ULL w23a = pk2(v2.x, v3.x), w23b = pk2(v2.y, v3.y);
        #pragma unroll
        for (int r = 0; r < 16; r++) {
            ulonglong2 x = sn[r * K4 + k4];
            ffma2(acc0[r], x.x, w01a);
            ffma2(acc0[r], x.y, w23a);
            ffma2(acc1[r], x.x, w01b);
            ffma2(acc1[r], x.y, w23b);
        }
    }
    #pragma unroll
    for (int r = 0; r < 16; r++) emit(r, fold2(acc0[r]), fold2(acc1[r]));
}

// =====================================================================
// L1 FRONT: h+el/er | drug score | Sdx static | edge count
// =====================================================================
__global__ void k_front(const float* __restrict__ dxEmb, const float* __restrict__ extra,
                        const float* __restrict__ W, const float* __restrict__ al,
                        const float* __restrict__ ar,
                        const float* __restrict__ drEmb, const float* __restrict__ drEmb2,
                        const float* __restrict__ attnW,
                        const int* __restrict__ edst) {
    __shared__ __align__(16) float4 sn4[32 * 64];   // 32KB
    __shared__ float pel[32][2];
    __shared__ float per[32][2];
    const int bid = blockIdx.x, tid = threadIdx.x;
    const int lane = tid & 31, wp2 = (tid >> 5) & 1;
    const int t64 = tid & 63, rowgrp = tid >> 6;
    const int c0 = 2 * t64;

    if (bid < B_H) {
        // ---- h = nodes @ gat_W (32 rows) + fused el/er ----
        const int r0 = bid * 32;
        for (int i = tid; i < 32 * 32; i += 128) {
            int rr = i >> 5, c4 = i & 31;
            int row = r0 + rr;
            float4 v = make_float4(0.f, 0.f, 0.f, 0.f);
            if (row < NNODE)
                v = (row < DXV) ? ((const float4*)dxEmb)[row * 32 + c4]
                                : ((const float4*)extra)[(row - DXV) * 32 + c4];
            sn4[i] = v;
        }
        __syncthreads();
        float2 al2 = __ldg((const float2*)(al + c0));
        float2 ar2 = __ldg((const float2*)(ar + c0));
        const ulonglong2* sn = (const ulonglong2*)sn4 + rowgrp * 16 * 32;
        gemm16x2<32>(sn, W + c0, Dm,
            [&](int rr, float v0, float v1) {
                int row = r0 + rowgrp * 16 + rr;
                if (row < NNODE) {
                    g_h[(long)row * Dm + c0]     = v0;
                    g_h[(long)row * Dm + c0 + 1] = v1;
                }
                float p = warpSum(v0 * al2.x + v1 * al2.y);
                float q = warpSum(v0 * ar2.x + v1 * ar2.y);
                if (lane == 0) {
                    pel[rowgrp * 16 + rr][wp2] = p;
                    per[rowgrp * 16 + rr][wp2] = q;
                }
            });
        __syncthreads();
        if (tid < 32) {
            int row = r0 + tid;
            if (row < NNODE) g_el[row] = pel[tid][0] + pel[tid][1];
        } else if (tid < 64) {
            int rr = tid - 32, row = r0 + rr;
            if (row < NNODE) g_er[row] = per[rr][0] + per[rr][1];
        }
    } else if (bid < B_H + B_DR) {
        // ---- drug score (K=256): drEmb@W[0:128] + drEmb2@W[128:256] ----
        const int r0 = (bid - B_H) * 32;
        for (int i = tid; i < 32 * 64; i += 128) {
            int rr = i >> 6, c4 = i & 63;
            int row = r0 + rr;
            float4 v = make_float4(0.f, 0.f, 0.f, 0.f);
            if (row < DRV)
                v = (c4 < 32) ? ((const float4*)drEmb)[row * 32 + c4]
                              : ((const float4*)drEmb2)[row * 32 + (c4 - 32)];
            sn4[i] = v;
        }
        __syncthreads();
        const ulonglong2* sn = (const ulonglong2*)sn4 + rowgrp * 16 * 64;
        gemm16x2<64>(sn, attnW + c0, Dm,
            [&](int rr, float v0, float v1) {
                int row = r0 + rowgrp * 16 + rr;
                if (row < DRV) {
                    g_Sdrug[(long)row * Dm + c0]     = v0;
                    g_Sdrug[(long)row * Dm + c0 + 1] = v1;
                }
            });
    } else if (bid < B_H + B_DR + B_SDX) {
        // ---- Sdx static half (K=128): dxEmb @ attnW[0:128] ----
        const int r0 = (bid - B_H - B_DR) * 32;
        for (int i = tid; i < 32 * 32; i += 128) {
            int rr = i >> 5, c4 = i & 31;
            int row = r0 + rr;
            sn4[i] = (row < DXV) ? ((const float4*)dxEmb)[row * 32 + c4]
                                 : make_float4(0.f, 0.f, 0.f, 0.f);
        }
        __syncthreads();
        const ulonglong2* sn = (const ulonglong2*)sn4 + rowgrp * 16 * 32;
        gemm16x2<32>(sn, attnW + c0, Dm,
            [&](int rr, float v0, float v1) {
                int row = r0 + rowgrp * 16 + rr;
                if (row < DXV) {
                    g_SdxA[(long)row * Dm + c0]     = v0;
                    g_SdxA[(long)row * Dm + c0 + 1] = v1;
                }
            });
    } else {
        // ---- edge count ----
        int cb = bid - B_H - B_DR - B_SDX;
        #pragma unroll
        for (int q = 0; q < 4; q++) {
            int i = cb * 512 + q * 128 + tid;
            if (i < ECNT) {
                int d = edst[i];
                if (d < DXV) g_rank[i] = atomicAdd(&g_count[d], 1);
            }
        }
    }
}

// =====================================================================
// L2: single-block two-level exclusive scan (1024 thr, 10 elems each)
// =====================================================================
__global__ void k_scan() {
    __shared__ int wsum[32];
    const int tid = threadIdx.x, l = tid & 31, w = tid >> 5;
    int pre[10];
    int s = 0;
    #pragma unroll
    for (int k = 0; k < 10; k++) {
        int idx = tid * 10 + k;
        int v = (idx < DXV) ? g_count[idx] : 0;
        pre[k] = s; s += v;
    }
    int x = s;
    #pragma unroll
    for (int o = 1; o < 32; o <<= 1) {
        int y = __shfl_up_sync(0xffffffffu, x, o);
        if (l >= o) x += y;
    }
    if (l == 31) wsum[w] = x;
    __syncthreads();
    if (w == 0) {
        int ws = wsum[l];
        #pragma unroll
        for (int o = 1; o < 32; o <<= 1) {
            int y = __shfl_up_sync(0xffffffffu, ws, o);
            if (l >= o) ws += y;
        }
        wsum[l] = ws;
    }
    __syncthreads();
    int texcl = ((w > 0) ? wsum[w - 1] : 0) + x - s;
    #pragma unroll
    for (int k = 0; k < 10; k++) {
        int idx = tid * 10 + k;
        if (idx < DXV) g_rowoff[idx] = texcl + pre[k];
    }
    if (tid == 0) g_rowoff[DXV] = wsum[31];
}

// =====================================================================
// L3: atomic-free scatter + re-zero counts + zero dxALLonto accumulator
// grid: 1250 x 256 = 320000 threads (covers all three jobs)
// =====================================================================
__global__ void k_scatter(const int* __restrict__ dst) {
    int i = blockIdx.x * blockDim.x + threadIdx.x;
    if (i < ECNT) {
        int d = dst[i];
        if (d < DXV) g_eid[g_rowoff[d] + g_rank[i]] = i;
    }
    if (i < DXV) g_count[i] = 0;
    if (i < ZV4) ((float4*)g_dxALLonto)[i] = make_float4(0.f, 0.f, 0.f, 0.f);
}

// =====================================================================
// L4 (profiled slot): dxALLonto = GAT-agg + classEmb, SPLIT across blocks.
//   bid <  DXV : GAT softmax-aggregate for row d=bid        -> atomicAdd
//   bid >= DXV : classEmb L2norm(A[d] @ S) for d=bid-DXV    -> atomicAdd
// Exactly two commutative fp adds per element (a+b == b+a bitwise)
// => result deterministic regardless of block order.
// =====================================================================
__global__ void k_aggCE(const int* __restrict__ esrc,
                        const float* __restrict__ A, const float* __restrict__ S) {
    const int tid = threadIdx.x;
    const int lane = tid & 31, w = tid >> 5;
    __shared__ int   sid[MAXDEG];
    __shared__ int   ssrc[MAXDEG];
    __shared__ float sw[MAXDEG];
    __shared__ float shred[4];

    if (blockIdx.x < DXV) {
        // ================= GAT aggregate =================
        const int d = blockIdx.x;
        __shared__ float spart[4][128];

        int base = g_rowoff[d];
        int n = g_rowoff[d + 1] - base;
        if (n > MAXDEG) n = MAXDEG;
        for (int j = tid; j < n; j += 128) sid[j] = g_eid[base + j];
        __syncthreads();
        // deterministic ascending edge-id order via rank sort (ids unique)
        for (int j = tid; j < n; j += 128) {
            int id = sid[j];
            int rk = 0;
            for (int k = 0; k < n; k++) rk += (sid[k] < id);
            ssrc[rk] = id;
        }
        __syncthreads();
        float er_d = g_er[d];
        for (int j = tid; j < n; j += 128) {
            int s = esrc[ssrc[j]];
            float x = g_el[s] + er_d;
            sw[j] = (x >= 0.f) ? x : 0.2f * x;
            ssrc[j] = s;
        }
        __syncthreads();
        float m = -1e30f;
        for (int j = tid; j < n; j += 128) m = fmaxf(m, sw[j]);
        m = blockMax128(m, shred);
        float ps = 0.f;
        for (int j = tid; j < n; j += 128) {
            float ww = __expf(sw[j] - m);
            sw[j] = ww;
            ps += ww;
        }
        float inv = 1.f / (blockSum128(ps, shred) + 1e-9f);

        // warp-split aggregate: warp w takes j ≡ w (mod 4); fixed order
        float a0 = 0.f, a1 = 0.f, a2 = 0.f, a3 = 0.f;
        #pragma unroll 2
        for (int j = w; j < n; j += 4) {
            float wt = sw[j];
            const float* hp = g_h + (long)ssrc[j] * Dm + lane;
            a0 += wt * hp[0];
            a1 += wt * hp[32];
            a2 += wt * hp[64];
            a3 += wt * hp[96];
        }
        spart[w][lane]      = a0;
        spart[w][lane + 32] = a1;
        spart[w][lane + 64] = a2;
        spart[w][lane + 96] = a3;
        __syncthreads();
        float acc = spart[0][tid] + spart[1][tid] + spart[2][tid] + spart[3][tid];
        atomicAdd(&g_dxALLonto[(long)d * Dm + tid], acc * inv);
    } else {
        // ================= classEmb =================
        const int d = blockIdx.x - DXV;
        __shared__ float sVr[ANCCAP];
        __shared__ int   sIr[ANCCAP];
        __shared__ float sV[ANCCAP];
        __shared__ int   sI[ANCCAP];
        __shared__ int   s_cnt;

        const float4* r4 = (const float4*)(A + (long)d * NANC);
        float4 va[4];
        #pragma unroll
        for (int q = 0; q < 4; q++) {
            int f4 = tid * 4 + q;
            va[q] = (f4 < NANC / 4) ? __ldg(r4 + f4) : make_float4(0.f, 0.f, 0.f, 0.f);
        }
        if (tid == 0) s_cnt = 0;
        __syncthreads();
        // shared-atomic append of nonzeros (order laundered by index sort)
        const float* vf = (const float*)va;
        #pragma unroll
        for (int t = 0; t < 16; t++) {
            float v = vf[t];
            if (v != 0.f) {
                int p = atomicAdd(&s_cnt, 1);
                if (p < ANCCAP) { sVr[p] = v; sIr[p] = tid * 16 + t; }
            }
        }
        __syncthreads();
        int cnt = s_cnt;
        if (cnt > ANCCAP) cnt = ANCCAP;
        // canonical sort by ancestor index (unique) => deterministic
        if (tid < cnt) {
            int my = sIr[tid];
            int rk = 0;
            for (int k = 0; k < cnt; k++) rk += (sIr[k] < my);
            sV[rk] = sVr[tid];
            sI[rk] = my;
        }
        __syncthreads();
        float ce = 0.f;
        #pragma unroll 2
        for (int j = 0; j < cnt; j++)
            ce += sV[j] * __ldg(S + sI[j] * Dm + tid);
        float ss = blockSum128(ce * ce, shred);
        float cen = ce / (sqrtf(ss) + 1e-12f);
        atomicAdd(&g_dxALLonto[(long)d * Dm + tid], cen);
    }
}

// =====================================================================
// L5: Sdx = SdxA + dxALLonto @ attnW[128:256]   (K=128 only)
// =====================================================================
__global__ void k_scoreDx2(const float* __restrict__ attnW) {
    __shared__ __align__(16) float4 sn4[32 * 32];   // 16KB
    const int tid = threadIdx.x;
    const int t64 = tid & 63, rowgrp = tid >> 6;
    const int c0 = 2 * t64;
    const int r0 = blockIdx.x * 32;
    for (int i = tid; i < 32 * 32; i += 128) {
        int rr = i >> 5, c4 = i & 31;
        int row = r0 + rr;
        sn4[i] = (row < DXV) ? ((const float4*)g_dxALLonto)[row * 32 + c4]
                             : make_float4(0.f, 0.f, 0.f, 0.f);
    }
    __syncthreads();
    const ulonglong2* sn = (const ulonglong2*)sn4 + rowgrp * 16 * 32;
    gemm16x2<32>(sn, attnW + Dm * Dm + c0, Dm,
        [&](int rr, float v0, float v1) {
            int row = r0 + rowgrp * 16 + rr;
            if (row < DXV) {
                float2 sa = __ldg((const float2*)(g_SdxA + (long)row * Dm + c0));
                g_Sdx[(long)row * Dm + c0]     = v0 + sa.x;
                g_Sdx[(long)row * Dm + c0 + 1] = v1 + sa.y;
            }
        });
}

// =====================================================================
// L6: per-visit attention
// =====================================================================
__global__ void k_visit(const int* __restrict__ dxseqs, const int* __restrict__ drugseqs,
                        const float* __restrict__ dxEmb, const float* __restrict__ drEmb,
                        const float* __restrict__ drEmb2, const float* __restrict__ attnW,
                        const float* __restrict__ attnB, const float* __restrict__ combW,
                        const float* __restrict__ combB) {
    const int bv = blockIdx.x, tid = threadIdx.x;
    __shared__ int   sh_idx[NCODE];
    __shared__ __align__(16) float s_u[256];
    __shared__ float s_up[Dm];
    __shared__ float s_sc[NCODE];
    __shared__ float s_alpha[NCODE];
    __shared__ float shred[4];

    if (tid < NDX)        sh_idx[tid] = dxseqs[bv * NDX + tid];
    else if (tid < NCODE) sh_idx[tid] = drugseqs[bv * NDX + (tid - NDX)];
    __syncthreads();

    float u0 = 0.f, u1 = 0.f;
    #pragma unroll 4
    for (int k = 0; k < NCODE; k++) {
        int id = sh_idx[k];
        const float *p0, *p1;
        if (k < NDX) { p0 = dxEmb + (long)id * Dm; p1 = g_dxALLonto + (long)id * Dm; }
        else         { p0 = drEmb + (long)id * Dm; p1 = drEmb2 + (long)id * Dm; }
        u0 += p0[tid];
        u1 += p1[tid];
    }
    s_u[tid] = u0 * (1.f / NCODE);
    s_u[Dm + tid] = u1 * (1.f / NCODE);
    __syncthreads();

    {   // u_part = u @ attnW[256:512] + attn_b   (k-paired FFMA2)
        const ULL* su64 = (const ULL*)s_u;
        ULL up2 = 0ull;
        #pragma unroll 4
        for (int k2 = 0; k2 < 128; k2++) {
            ULL wv = pk2(__ldg(attnW + (256 + 2 * k2) * Dm + tid),
                         __ldg(attnW + (257 + 2 * k2) * Dm + tid));
            ffma2(up2, su64[k2], wv);
        }
        s_up[tid] = __ldg(attnB + tid) + fold2(up2);
    }
    __syncthreads();

    const int w = tid >> 5, lane = tid & 31;
    const float cb = __ldg(combB);
    for (int k = w; k < NCODE; k += 4) {
        int id = sh_idx[k];
        const float* base = (k < NDX) ? (g_Sdx + (long)id * Dm) : (g_Sdrug + (long)id * Dm);
        float t = 0.f;
        #pragma unroll
        for (int q = 0; q < 4; q++) {
            int dcol = lane + 32 * q;
            t += fast_tanh(base[dcol] + s_up[dcol]) * __ldg(combW + dcol);
        }
        t = warpSum(t);
        if (lane == 0) s_sc[k] = t + cb;
    }
    __syncthreads();

    float sv = (tid < NCODE) ? s_sc[tid] : -1e30f;
    float m = blockMax128(sv, shred);
    float e = (tid < NCODE) ? __expf(sv - m) : 0.f;
    float Z = blockSum128(e, shred);
    if (tid < NCODE) s_alpha[tid] = e / Z;
    __syncthreads();

    float v0 = 0.f, v1 = 0.f;
    #pragma unroll 4
    for (int k = 0; k < NCODE; k++) {
        float a = s_alpha[k];
        int id = sh_idx[k];
        const float *p0, *p1;
        if (k < NDX) { p0 = dxEmb + (long)id * Dm; p1 = g_dxALLonto + (long)id * Dm; }
        else         { p0 = drEmb + (long)id * Dm; p1 = drEmb2 + (long)id * Dm; }
        v0 += a * p0[tid];
        v1 += a * p1[tid];
    }
    g_visit[bv * 256 + tid] = v0;
    g_visit[bv * 256 + Dm + tid] = v1;
}

// =====================================================================
// L7: out = sigmoid(visit @ dp_W + dp_b)   (32 rows x 128 cols per block)
// =====================================================================
__global__ void k_dp(const float* __restrict__ dpW, const float* __restrict__ dpB,
                     float* __restrict__ out) {
    __shared__ __align__(16) float4 sv4[32 * 64];   // 32KB
    const int tid = threadIdx.x;
    const int t64 = tid & 63, rowgrp = tid >> 6;
    const int c0 = blockIdx.x * 128 + 2 * t64;
    const int r0 = blockIdx.y * 32;
    for (int i = tid; i < 32 * 64; i += 128)
        sv4[i] = ((const float4*)g_visit)[r0 * 64 + i];
    __syncthreads();
    if (c0 >= LBL) return;   // LBL even -> pairs never straddle
    float2 b2 = __ldg((const float2*)(dpB + c0));
    const ulonglong2* sn = (const ulonglong2*)sv4 + rowgrp * 16 * 64;
    gemm16x2<64>(sn, dpW + c0, LBL,
        [&](int rr, float v0, float v1) {
            int row = r0 + rowgrp * 16 + rr;
            out[(long)row * LBL + c0]     = 1.f / (1.f + __expf(-(v0 + b2.x)));
            out[(long)row * LBL + c0 + 1] = 1.f / (1.f + __expf(-(v1 + b2.y)));
        });
}

// ---------------- launcher ----------------
extern "C" void kernel_launch(void* const* d_in, const int* in_sizes, int n_in,
                              void* d_out, int out_size) {
    const int*   dxseqs  = (const int*)d_in[0];
    const int*   drugseqs= (const int*)d_in[1];
    const int*   esrc    = (const int*)d_in[2];
    const int*   edst    = (const int*)d_in[3];
    const float* dx2anc  = (const float*)d_in[4];
    const float* dxEmb   = (const float*)d_in[5];
    const float* drEmb   = (const float*)d_in[6];
    const float* drEmb2  = (const float*)d_in[7];
    const float* extra   = (const float*)d_in[8];
    const float* S       = (const float*)d_in[9];
    const float* gatW    = (const float*)d_in[10];
    const float* gal     = (const float*)d_in[11];
    const float* gar     = (const float*)d_in[12];
    const float* attnW   = (const float*)d_in[13];
    const float* attnB   = (const float*)d_in[14];
    const float* combW   = (const float*)d_in[15];
    const float* combB   = (const float*)d_in[16];
    const float* dpW     = (const float*)d_in[17];
    const float* dpB     = (const float*)d_in[18];
    float*       out     = (float*)d_out;

    // k_aggCE (split agg | classEmb blocks) lands in profiled slot 4.
    k_front<<<B_H + B_DR + B_SDX + B_CNT, 128>>>(dxEmb, extra, gatW, gal, gar,
                                                 drEmb, drEmb2, attnW, edst);
    k_scan<<<1, 1024>>>();
    k_scatter<<<(ZV4 + 255) / 256, 256>>>(edst);
    k_aggCE<<<2 * DXV, 128>>>(esrc, dx2anc, S);
    k_scoreDx2<<<B_SDX, 128>>>(attnW);
    k_visit<<<NBV, 128>>>(dxseqs, drugseqs, dxEmb, drEmb, drEmb2,
                          attnW, attnB, combW, combB);
    k_dp<<<dim3((LBL + 127) / 128, NBV / 32), 128>>>(dpW, dpB, out);
}